// round 5
// baseline (speedup 1.0000x reference)
#include <cuda_runtime.h>
#include <math.h>
#include <stdint.h>

#define D_NODE 100
#define D_EDGE 172
#define D_TIME 100
#define NKV    372
#define DOUT   100
#define EMAX   320000
#define DMAX   20000
#define MINN   1e-15f
#define MAXN   0.996f
#define SLOPE  0.2f

__device__ float    g_Qd[DMAX * DOUT];
__device__ float    g_dsthyp[DMAX * D_NODE];
__device__ float    g_V[(size_t)EMAX * DOUT];
__device__ float    g_scores[EMAX * 2];
__device__ float    g_ez[EMAX * 2];
__device__ unsigned g_smax[DMAX * 2];
__device__ float    g_ssum[DMAX * 2];
__device__ float    g_hagg[DMAX * DOUT];
__device__ float    g_hb[4 * DOUT];
__device__ float    g_hb2[4];
__device__ float    g_ztf[D_TIME];
__device__ float    g_ztf_e2;

__device__ __forceinline__ float wsum32(float v) {
#pragma unroll
    for (int m = 16; m; m >>= 1) v += __shfl_xor_sync(0xffffffffu, v, m);
    return v;
}
__device__ __forceinline__ float wsum16(float v) {
#pragma unroll
    for (int m = 8; m; m >>= 1) v += __shfl_xor_sync(0xffffffffu, v, m);
    return v;
}
__device__ __forceinline__ float artanh_f(float x) {
    x = fminf(fmaxf(x, -1.0f + 1e-7f), 1.0f - 1e-7f);
    return 0.5f * (log1pf(x) - log1pf(-x));
}
__device__ __forceinline__ void enc_scale(float ss, float& s, float& en) {
    float n = sqrtf(ss), nn = fmaxf(n, MINN);
    float t = tanhf(nn);
    en = fminf(t, MAXN);
    s = en / nn;
}
__device__ __forceinline__ void hyp_ab(float mxn2, float xn, float dot_mh, float hb2,
                                       float& alpha, float& beta, float& nprev) {
    float mxn = fmaxf(sqrtf(mxn2), MINN);
    float t = tanhf(mxn / xn * artanh_f(xn));
    float nres = fminf(t, MAXN);
    float s1 = nres / mxn;
    float x2 = nres * nres;
    float xy = s1 * dot_mh;
    float a = 1.f + 2.f * xy + hb2;
    float bb = 1.f - x2;
    float den = fmaxf(1.f + 2.f * xy + x2 * hb2, MINN);
    float n2 = fmaxf(a * a * x2 + 2.f * a * bb * xy + bb * bb * hb2, 0.f);
    float nout = sqrtf(n2) / den;
    float ps = nout > MAXN ? MAXN / nout : 1.f;
    alpha = ps * a * s1 / den;
    beta = ps * bb / den;
    nprev = fminf(nout, MAXN);
}
__device__ __forceinline__ unsigned fenc(float f) {
    unsigned b = __float_as_uint(f);
    return (b & 0x80000000u) ? ~b : (b | 0x80000000u);
}
__device__ __forceinline__ float fdec(unsigned u) {
    return __uint_as_float((u & 0x80000000u) ? (u & 0x7fffffffu) : ~u);
}
__device__ __forceinline__ float lrelu(float x) { return x > 0.f ? x : SLOPE * x; }

// ---------------- k0: zero accumulators --------------------------------------
__global__ void k_zero(int D) {
    int tid = blockIdx.x * blockDim.x + threadIdx.x;
    int nt = gridDim.x * blockDim.x;
    for (int i = tid; i < D * DOUT; i += nt) g_hagg[i] = 0.f;
    for (int i = tid; i < 2 * D; i += nt) { g_ssum[i] = 0.f; g_smax[i] = 0u; }
}

// ---------------- k_small: hb vectors + ztf ----------------------------------
__global__ void k_small(const float* __restrict__ bq, const float* __restrict__ bk,
                        const float* __restrict__ bv, const float* __restrict__ bo,
                        const float* __restrict__ tb) {
    int w = threadIdx.x >> 5, l = threadIdx.x & 31;
    if (w < 5) {
        const float* bp = (w == 0) ? bq : (w == 1) ? bk : (w == 2) ? bv : (w == 3) ? bo : tb;
        float v[4]; float ss = 0.f;
#pragma unroll
        for (int m = 0; m < 4; ++m) {
            int o = l + 32 * m;
            float x = (o < DOUT) ? bp[o] : 0.f;
            if (w == 4) x = cosf(x);
            v[m] = (o < DOUT) ? x : 0.f;
            ss += v[m] * v[m];
        }
        ss = wsum32(ss);
        float s, en; enc_scale(ss, s, en);
#pragma unroll
        for (int m = 0; m < 4; ++m) {
            int o = l + 32 * m;
            if (o < DOUT) { if (w < 4) g_hb[w * DOUT + o] = v[m] * s; else g_ztf[o] = v[m] * s; }
        }
        if (l == 0) { if (w < 4) g_hb2[w] = en * en; else g_ztf_e2 = en * en; }
    }
}

// ---------------- k1: per-dst encode + Q projection --------------------------
__global__ void __launch_bounds__(256) k1_dst(const float* __restrict__ dst_h,
                                              const float* __restrict__ Wq, int D) {
    extern __shared__ float sm[];
    float* Ws = sm;               // [200][133] -> reused as M [32][104]
    float* Xs = sm + 200 * 133;   // [32][200]
    __shared__ float s_xn[32];
    int t = threadIdx.x, w = t >> 5, l = t & 31;
    int rbase = blockIdx.x * 32;
    float ztf_e2 = g_ztf_e2;
    for (int i = 0; i < 4; ++i) {
        int r = w * 4 + i, gr = rbase + r;
        float* xr = Xs + r * 200;
        if (gr < D) {
            const float* dr = dst_h + (size_t)gr * D_NODE;
            float v[4]; float ss = 0.f;
#pragma unroll
            for (int m = 0; m < 4; ++m) { int o = l + 32 * m; v[m] = (o < 100) ? dr[o] : 0.f; ss += v[m] * v[m]; }
            ss = wsum32(ss);
            float s, en; enc_scale(ss, s, en);
#pragma unroll
            for (int m = 0; m < 4; ++m) {
                int o = l + 32 * m;
                if (o < 100) {
                    float h = v[m] * s;
                    xr[o] = h; xr[100 + o] = g_ztf[o];
                    g_dsthyp[(size_t)gr * 100 + o] = h;
                }
            }
            if (l == 0) s_xn[r] = fmaxf(sqrtf(en * en + ztf_e2), MINN);
        } else {
            for (int o = l; o < 200; o += 32) xr[o] = 0.f;
            if (l == 0) s_xn[r] = MINN;
        }
    }
    for (int i = t; i < 28 * 200; i += 256) { int o = 100 + i / 200, k = i % 200; Ws[k * 133 + o] = 0.f; }
    for (int i = t; i < 100 * 200; i += 256) { int o = i / 200, k = i % 200; Ws[k * 133 + o] = Wq[i]; }
    __syncthreads();
    int oc = t & 127, g = t >> 7;
    float acc[16];
#pragma unroll
    for (int rr = 0; rr < 16; ++rr) acc[rr] = 0.f;
    for (int k = 0; k < 200; ++k) {
        float wv = Ws[k * 133 + oc];
#pragma unroll
        for (int rr = 0; rr < 16; ++rr) acc[rr] = fmaf(Xs[(g * 16 + rr) * 200 + k], wv, acc[rr]);
    }
    __syncthreads();
    float* Ms = Ws;
    if (oc < 100) {
#pragma unroll
        for (int rr = 0; rr < 16; ++rr) Ms[(g * 16 + rr) * 104 + oc] = acc[rr];
    }
    __syncthreads();
    float hb2 = g_hb2[0];
    for (int i = 0; i < 4; ++i) {
        int r = w * 4 + i, gr = rbase + r;
        if (gr >= D) continue;
        float mv[4], hv[4]; float pn = 0.f, pd = 0.f;
#pragma unroll
        for (int m = 0; m < 4; ++m) {
            int o = l + 32 * m;
            float a = (o < 100) ? Ms[r * 104 + o] : 0.f;
            float h = (o < 100) ? g_hb[o] : 0.f;
            mv[m] = a; hv[m] = h; pn += a * a; pd += a * h;
        }
        pn = wsum32(pn); pd = wsum32(pd);
        float alpha, beta, np;
        hyp_ab(pn, s_xn[r], pd, hb2, alpha, beta, np);
#pragma unroll
        for (int m = 0; m < 4; ++m) {
            int o = l + 32 * m;
            if (o < 100) g_Qd[(size_t)gr * 100 + o] = alpha * mv[m] + beta * hv[m];
        }
    }
}

// ---------------- k2: fused edge encode + joint K/V GEMM + scores ------------
#define TE    64
#define KC    124
#define WP    132
#define XPAD  380
__global__ void __launch_bounds__(512) k2_edge(
    const float* __restrict__ neigh, const float* __restrict__ edgef,
    const float* __restrict__ dtp, const int* __restrict__ edst,
    const float* __restrict__ Wk, const float* __restrict__ Wv,
    const float* __restrict__ tw, const float* __restrict__ tb, int E) {
    extern __shared__ float sm[];
    float* Xs  = sm;                       // [64][380]
    float* Wks = sm + TE * XPAD;           // [124][132] -> reused as Kt [64][104]
    float* Wvs = Wks + KC * WP;            // [124][132]
    __shared__ float s_xn[TE];
    __shared__ int   s_dst[TE];
    __shared__ float s_hbk[DOUT], s_hbv[DOUT];
    __shared__ float s_hb2k, s_hb2v;
    int t = threadIdx.x, w = t >> 5, l = t & 31;
    int base = blockIdx.x * TE;

    // Phase A: build encoded X rows (16 warps x 4 edges)
    for (int i = 0; i < 4; ++i) {
        int e = w * 4 + i, ge = base + e;
        float* xr = Xs + e * XPAD;
        if (ge < E) {
            float ss, s, e1, e2, e3;
            const float* nr = neigh + (size_t)ge * D_NODE;
            float v[4]; ss = 0.f;
#pragma unroll
            for (int m = 0; m < 4; ++m) { int o = l + 32 * m; v[m] = (o < 100) ? nr[o] : 0.f; ss += v[m] * v[m]; }
            ss = wsum32(ss); enc_scale(ss, s, e1);
#pragma unroll
            for (int m = 0; m < 4; ++m) { int o = l + 32 * m; if (o < 100) xr[o] = v[m] * s; }
            const float* er2 = edgef + (size_t)ge * D_EDGE;
            float u[6]; ss = 0.f;
#pragma unroll
            for (int m = 0; m < 6; ++m) { int o = l + 32 * m; u[m] = (o < 172) ? er2[o] : 0.f; ss += u[m] * u[m]; }
            ss = wsum32(ss); enc_scale(ss, s, e2);
#pragma unroll
            for (int m = 0; m < 6; ++m) { int o = l + 32 * m; if (o < 172) xr[100 + o] = u[m] * s; }
            float dtv = dtp[ge];
            float cc[4]; ss = 0.f;
#pragma unroll
            for (int m = 0; m < 4; ++m) {
                int o = l + 32 * m;
                float c = (o < 100) ? __cosf(fmaf(dtv, tw[o], tb[o])) : 0.f;
                cc[m] = c; ss += c * c;
            }
            ss = wsum32(ss); enc_scale(ss, s, e3);
#pragma unroll
            for (int m = 0; m < 4; ++m) { int o = l + 32 * m; if (o < 100) xr[272 + o] = cc[m] * s; }
            if (l == 0) { s_xn[e] = fmaxf(sqrtf(e1 * e1 + e2 * e2 + e3 * e3), MINN); s_dst[e] = edst[ge]; }
        } else {
            for (int o = l; o < NKV; o += 32) xr[o] = 0.f;
            if (l == 0) { s_xn[e] = MINN; s_dst[e] = 0; }
        }
    }
    // hb's + zero-pad weight cols [100,128)
    for (int o = t; o < DOUT; o += 512) { s_hbk[o] = g_hb[1 * DOUT + o]; s_hbv[o] = g_hb[2 * DOUT + o]; }
    if (t == 0) { s_hb2k = g_hb2[1]; s_hb2v = g_hb2[2]; }
    for (int i = t; i < KC * 28; i += 512) {
        int kk = i / 28, o = 100 + i % 28;
        Wks[kk * WP + o] = 0.f; Wvs[kk * WP + o] = 0.f;
    }

    int g = t >> 4;            // 0..31 -> 2 edges each
    int oc = (t & 15) * 8;     // 0..120
    int er = g * 2;
    float aK[2][8], aV[2][8];
#pragma unroll
    for (int i2 = 0; i2 < 2; ++i2)
#pragma unroll
        for (int j = 0; j < 8; ++j) { aK[i2][j] = 0.f; aV[i2][j] = 0.f; }

    for (int kc = 0; kc < NKV; kc += KC) {
        __syncthreads();
        for (int i = t; i < 100 * KC; i += 512) {
            int o = i / KC, kk = i % KC;
            Wks[kk * WP + o] = Wk[o * NKV + kc + kk];
            Wvs[kk * WP + o] = Wv[o * NKV + kc + kk];
        }
        __syncthreads();
        for (int kk = 0; kk < KC; kk += 4) {
            float4 xa = *(const float4*)(Xs + er * XPAD + kc + kk);
            float4 xb = *(const float4*)(Xs + (er + 1) * XPAD + kc + kk);
            const float* xap = (const float*)&xa;
            const float* xbp = (const float*)&xb;
#pragma unroll
            for (int u = 0; u < 4; ++u) {
                float4 k0 = *(const float4*)(Wks + (kk + u) * WP + oc);
                float4 k1 = *(const float4*)(Wks + (kk + u) * WP + oc + 4);
                float4 v0 = *(const float4*)(Wvs + (kk + u) * WP + oc);
                float4 v1 = *(const float4*)(Wvs + (kk + u) * WP + oc + 4);
                float xau = xap[u], xbu = xbp[u];
                const float* kp0 = (const float*)&k0; const float* kp1 = (const float*)&k1;
                const float* vp0 = (const float*)&v0; const float* vp1 = (const float*)&v1;
#pragma unroll
                for (int j = 0; j < 4; ++j) {
                    aK[0][j]     = fmaf(xau, kp0[j], aK[0][j]);
                    aK[0][j + 4] = fmaf(xau, kp1[j], aK[0][j + 4]);
                    aK[1][j]     = fmaf(xbu, kp0[j], aK[1][j]);
                    aK[1][j + 4] = fmaf(xbu, kp1[j], aK[1][j + 4]);
                    aV[0][j]     = fmaf(xau, vp0[j], aV[0][j]);
                    aV[0][j + 4] = fmaf(xau, vp1[j], aV[0][j + 4]);
                    aV[1][j]     = fmaf(xbu, vp0[j], aV[1][j]);
                    aV[1][j + 4] = fmaf(xbu, vp1[j], aV[1][j + 4]);
                }
            }
        }
    }

    // epilogues: per-edge scalars
    float alK[2], beK[2], alV[2], beV[2];
#pragma unroll
    for (int i2 = 0; i2 < 2; ++i2) {
        float pnk = 0.f, pdk = 0.f, pnv = 0.f, pdv = 0.f;
#pragma unroll
        for (int j = 0; j < 8; ++j) {
            int o = oc + j;
            float hk = (o < DOUT) ? s_hbk[o] : 0.f;
            float hv = (o < DOUT) ? s_hbv[o] : 0.f;
            pnk += aK[i2][j] * aK[i2][j]; pdk += aK[i2][j] * hk;
            pnv += aV[i2][j] * aV[i2][j]; pdv += aV[i2][j] * hv;
        }
        pnk = wsum16(pnk); pdk = wsum16(pdk);
        pnv = wsum16(pnv); pdv = wsum16(pdv);
        float np;
        hyp_ab(pnk, s_xn[er + i2], pdk, s_hb2k, alK[i2], beK[i2], np);
        hyp_ab(pnv, s_xn[er + i2], pdv, s_hb2v, alV[i2], beV[i2], np);
    }

    // K tile to smem (reuse Wks), then scores
    __syncthreads();
    float* Kt = Wks;
#pragma unroll
    for (int i2 = 0; i2 < 2; ++i2)
#pragma unroll
        for (int j = 0; j < 8; ++j) {
            int o = oc + j;
            if (o < DOUT) Kt[(er + i2) * 104 + o] = alK[i2] * aK[i2][j] + beK[i2] * s_hbk[o];
        }
    __syncthreads();
    for (int i = 0; i < 4; ++i) {
        int e = w * 4 + i, ge = base + e;
        if (ge >= E) continue;
        int dv = s_dst[e];
        const float* q = g_Qd + (size_t)dv * DOUT;
        float s0 = 0.f, s1v = 0.f;
        for (int o = l; o < DOUT; o += 32) {
            float p = q[o] * Kt[e * 104 + o];
            if (o < 50) s0 += p; else s1v += p;
        }
        s0 = wsum32(s0); s1v = wsum32(s1v);
        if (l == 0) {
            float r0 = lrelu(s0), r1 = lrelu(s1v);
            g_scores[2 * ge] = r0; g_scores[2 * ge + 1] = r1;
            atomicMax(&g_smax[2 * dv], fenc(r0));
            atomicMax(&g_smax[2 * dv + 1], fenc(r1));
        }
    }
    // V to global (float4)
#pragma unroll
    for (int i2 = 0; i2 < 2; ++i2) {
        int ge = base + er + i2;
        if (ge >= E) continue;
        float* vp = g_V + (size_t)ge * DOUT + oc;
#pragma unroll
        for (int j4 = 0; j4 < 2; ++j4) {
            if (oc + j4 * 4 < DOUT) {
                float4 r;
                r.x = alV[i2] * aV[i2][j4 * 4 + 0] + beV[i2] * s_hbv[oc + j4 * 4 + 0];
                r.y = alV[i2] * aV[i2][j4 * 4 + 1] + beV[i2] * s_hbv[oc + j4 * 4 + 1];
                r.z = alV[i2] * aV[i2][j4 * 4 + 2] + beV[i2] * s_hbv[oc + j4 * 4 + 2];
                r.w = alV[i2] * aV[i2][j4 * 4 + 3] + beV[i2] * s_hbv[oc + j4 * 4 + 3];
                *(float4*)(vp + j4 * 4) = r;
            }
        }
    }
}

// ---------------- k3: exp + segment sum --------------------------------------
__global__ void k3_exp(const int* __restrict__ edst, int E) {
    int e = blockIdx.x * blockDim.x + threadIdx.x;
    if (e >= E) return;
    int d = edst[e];
    float z0 = __expf(g_scores[2 * e] - fdec(g_smax[2 * d]));
    float z1 = __expf(g_scores[2 * e + 1] - fdec(g_smax[2 * d + 1]));
    g_ez[2 * e] = z0; g_ez[2 * e + 1] = z1;
    atomicAdd(&g_ssum[2 * d], z0);
    atomicAdd(&g_ssum[2 * d + 1], z1);
}

// ---------------- k4: weighted scatter aggregate (vector red) ----------------
__global__ void k4_agg(const int* __restrict__ edst, int E) {
    int gw = (blockIdx.x * blockDim.x + threadIdx.x) >> 5;
    int l = threadIdx.x & 31;
    if (gw >= E) return;
    int d = edst[gw];
    float a0 = g_ez[2 * gw] / fmaxf(g_ssum[2 * d], MINN);
    float a1 = g_ez[2 * gw + 1] / fmaxf(g_ssum[2 * d + 1], MINN);
    if (l < 25) {
        const float4* vr = (const float4*)(g_V + (size_t)gw * DOUT);
        float4 v = vr[l];
        int c0 = 4 * l;
        float4 r;
        r.x = v.x * (c0 + 0 < 50 ? a0 : a1);
        r.y = v.y * (c0 + 1 < 50 ? a0 : a1);
        r.z = v.z * (c0 + 2 < 50 ? a0 : a1);
        r.w = v.w * (c0 + 3 < 50 ? a0 : a1);
        float* hp = g_hagg + (size_t)d * DOUT + c0;
        asm volatile("red.global.add.v4.f32 [%0], {%1, %2, %3, %4};"
                     :: "l"(hp), "f"(r.x), "f"(r.y), "f"(r.z), "f"(r.w) : "memory");
    }
}

// ---------------- k5: O projection + HypAct + logmap0 + LayerNorm ------------
__global__ void __launch_bounds__(256) k5_final(const float* __restrict__ Wo,
                                                const float* __restrict__ lng,
                                                const float* __restrict__ lnb,
                                                float* __restrict__ out, int D) {
    extern __shared__ float sm[];
    float* Ws = sm;
    float* Xs = sm + 200 * 133;
    __shared__ float s_xn[32];
    int t = threadIdx.x, w = t >> 5, l = t & 31;
    int rbase = blockIdx.x * 32;
    for (int i = 0; i < 4; ++i) {
        int r = w * 4 + i, gr = rbase + r;
        float* xr = Xs + r * 200;
        if (gr < D) {
            const float* ha = g_hagg + (size_t)gr * DOUT;
            const float* dh = g_dsthyp + (size_t)gr * D_NODE;
            float ss = 0.f;
#pragma unroll
            for (int m = 0; m < 4; ++m) {
                int o = l + 32 * m;
                float a = (o < 100) ? ha[o] : 0.f;
                float b = (o < 100) ? dh[o] : 0.f;
                if (o < 100) { xr[o] = a; xr[100 + o] = b; }
                ss += a * a + b * b;
            }
            ss = wsum32(ss);
            if (l == 0) s_xn[r] = fmaxf(sqrtf(ss), MINN);
        } else {
            for (int o = l; o < 200; o += 32) xr[o] = 0.f;
            if (l == 0) s_xn[r] = MINN;
        }
    }
    for (int i = t; i < 28 * 200; i += 256) { int o = 100 + i / 200, k = i % 200; Ws[k * 133 + o] = 0.f; }
    for (int i = t; i < 100 * 200; i += 256) { int o = i / 200, k = i % 200; Ws[k * 133 + o] = Wo[i]; }
    __syncthreads();
    int oc = t & 127, g = t >> 7;
    float acc[16];
#pragma unroll
    for (int rr = 0; rr < 16; ++rr) acc[rr] = 0.f;
    for (int k = 0; k < 200; ++k) {
        float wv = Ws[k * 133 + oc];
#pragma unroll
        for (int rr = 0; rr < 16; ++rr) acc[rr] = fmaf(Xs[(g * 16 + rr) * 200 + k], wv, acc[rr]);
    }
    __syncthreads();
    float* Ms = Ws;
    if (oc < 100) {
#pragma unroll
        for (int rr = 0; rr < 16; ++rr) Ms[(g * 16 + rr) * 104 + oc] = acc[rr];
    }
    __syncthreads();
    float hb2 = g_hb2[3];
    for (int i = 0; i < 4; ++i) {
        int r = w * 4 + i, gr = rbase + r;
        if (gr >= D) continue;
        float mv[4], hv[4]; float pn = 0.f, pd = 0.f;
#pragma unroll
        for (int m = 0; m < 4; ++m) {
            int o = l + 32 * m;
            float a = (o < 100) ? Ms[r * 104 + o] : 0.f;
            float h = (o < 100) ? g_hb[3 * DOUT + o] : 0.f;
            mv[m] = a; hv[m] = h; pn += a * a; pd += a * h;
        }
        pn = wsum32(pn); pd = wsum32(pd);
        float alpha, beta, nprev;
        hyp_ab(pn, s_xn[r], pd, hb2, alpha, beta, nprev);
        float lc = artanh_f(nprev) / fmaxf(nprev, MINN);
        float u2v[4]; float uss = 0.f;
#pragma unroll
        for (int m = 0; m < 4; ++m) {
            float u2 = lrelu(lc * (alpha * mv[m] + beta * hv[m]));
            u2v[m] = u2; uss += u2 * u2;
        }
        uss = wsum32(uss);
        float s2, en3; enc_scale(uss, s2, en3);
        float hsc = artanh_f(en3) / fmaxf(en3, MINN) * s2;
        float hvv[4]; float hs = 0.f, hs2 = 0.f;
#pragma unroll
        for (int m = 0; m < 4; ++m) {
            int o = l + 32 * m;
            float h = hsc * u2v[m];
            hvv[m] = h;
            if (o < 100) { hs += h; hs2 += h * h; }
        }
        hs = wsum32(hs); hs2 = wsum32(hs2);
        float mu = hs * 0.01f;
        float var = hs2 * 0.01f - mu * mu;
        float inv = rsqrtf(var + 1e-5f);
#pragma unroll
        for (int m = 0; m < 4; ++m) {
            int o = l + 32 * m;
            if (o < 100) out[(size_t)gr * 100 + o] = (hvv[m] - mu) * inv * lng[o] + lnb[o];
        }
    }
}

extern "C" void kernel_launch(void* const* d_in, const int* in_sizes, int n_in,
                              void* d_out, int out_size) {
    const float* dst_h = (const float*)d_in[0];
    const float* neigh = (const float*)d_in[1];
    const float* edgef = (const float*)d_in[2];
    const float* dtp   = (const float*)d_in[3];
    const int*   edst  = (const int*)d_in[4];
    const float* Wq = (const float*)d_in[5];
    const float* bq = (const float*)d_in[6];
    const float* Wk = (const float*)d_in[7];
    const float* bk = (const float*)d_in[8];
    const float* Wv = (const float*)d_in[9];
    const float* bv = (const float*)d_in[10];
    const float* Wo = (const float*)d_in[11];
    const float* bo = (const float*)d_in[12];
    const float* tw = (const float*)d_in[13];
    const float* tb = (const float*)d_in[14];
    const float* lng = (const float*)d_in[15];
    const float* lnb = (const float*)d_in[16];
    float* out = (float*)d_out;
    int D = in_sizes[0] / D_NODE;
    int E = in_sizes[3];

    size_t smem1 = (200 * 133 + 32 * 200) * sizeof(float);          // 132000
    size_t smem2 = (TE * XPAD + 2 * KC * WP) * sizeof(float);       // 228224
    cudaFuncSetAttribute(k1_dst,   cudaFuncAttributeMaxDynamicSharedMemorySize, (int)smem1);
    cudaFuncSetAttribute(k5_final, cudaFuncAttributeMaxDynamicSharedMemorySize, (int)smem1);
    cudaFuncSetAttribute(k2_edge,  cudaFuncAttributeMaxDynamicSharedMemorySize, (int)smem2);

    k_zero<<<2048, 256>>>(D);
    k_small<<<1, 160>>>(bq, bk, bv, bo, tb);
    k1_dst<<<(D + 31) / 32, 256, smem1>>>(dst_h, Wq, D);
    k2_edge<<<(E + TE - 1) / TE, 512, smem2>>>(neigh, edgef, dtp, edst, Wk, Wv, tw, tb, E);
    k3_exp<<<(E + 255) / 256, 256>>>(edst, E);
    k4_agg<<<(E + 7) / 8, 256>>>(edst, E);
    k5_final<<<(D + 31) / 32, 256, smem1>>>(Wo, lng, lnb, out, D);
}

// round 6
// speedup vs baseline: 2.5076x; 2.5076x over previous
#include <cuda_runtime.h>
#include <math.h>
#include <stdint.h>

#define D_NODE 100
#define D_EDGE 172
#define D_TIME 100
#define NKV    372
#define DOUT   100
#define EMAX   320000
#define DMAX   20000
#define MINN   1e-15f
#define MAXN   0.996f
#define SLOPE  0.2f

__device__ float    g_Qd[DMAX * DOUT];
__device__ float    g_dsthyp[DMAX * D_NODE];
__device__ float    g_V[(size_t)EMAX * DOUT];
__device__ float    g_scores[EMAX * 2];
__device__ float    g_ez[EMAX * 2];
__device__ unsigned g_smax[DMAX * 2];
__device__ float    g_ssum[DMAX * 2];
__device__ float    g_hagg[DMAX * DOUT];
__device__ float    g_hb[4 * DOUT];
__device__ float    g_hb2[4];
__device__ float    g_ztf[D_TIME];
__device__ float    g_ztf_e2;

__device__ __forceinline__ float wsum32(float v) {
#pragma unroll
    for (int m = 16; m; m >>= 1) v += __shfl_xor_sync(0xffffffffu, v, m);
    return v;
}
__device__ __forceinline__ float artanh_f(float x) {
    x = fminf(fmaxf(x, -1.0f + 1e-7f), 1.0f - 1e-7f);
    return 0.5f * (log1pf(x) - log1pf(-x));
}
__device__ __forceinline__ void enc_scale(float ss, float& s, float& en) {
    float n = sqrtf(ss), nn = fmaxf(n, MINN);
    float t = tanhf(nn);
    en = fminf(t, MAXN);
    s = en / nn;
}
__device__ __forceinline__ void hyp_ab(float mxn2, float xn, float dot_mh, float hb2,
                                       float& alpha, float& beta, float& nprev) {
    float mxn = fmaxf(sqrtf(mxn2), MINN);
    float t = tanhf(mxn / xn * artanh_f(xn));
    float nres = fminf(t, MAXN);
    float s1 = nres / mxn;
    float x2 = nres * nres;
    float xy = s1 * dot_mh;
    float a = 1.f + 2.f * xy + hb2;
    float bb = 1.f - x2;
    float den = fmaxf(1.f + 2.f * xy + x2 * hb2, MINN);
    float n2 = fmaxf(a * a * x2 + 2.f * a * bb * xy + bb * bb * hb2, 0.f);
    float nout = sqrtf(n2) / den;
    float ps = nout > MAXN ? MAXN / nout : 1.f;
    alpha = ps * a * s1 / den;
    beta = ps * bb / den;
    nprev = fminf(nout, MAXN);
}
__device__ __forceinline__ unsigned fenc(float f) {
    unsigned b = __float_as_uint(f);
    return (b & 0x80000000u) ? ~b : (b | 0x80000000u);
}
__device__ __forceinline__ float fdec(unsigned u) {
    return __uint_as_float((u & 0x80000000u) ? (u & 0x7fffffffu) : ~u);
}
__device__ __forceinline__ float lrelu(float x) { return x > 0.f ? x : SLOPE * x; }

// ---------------- k0: zero accumulators --------------------------------------
__global__ void k_zero(int D) {
    int tid = blockIdx.x * blockDim.x + threadIdx.x;
    int nt = gridDim.x * blockDim.x;
    for (int i = tid; i < D * DOUT; i += nt) g_hagg[i] = 0.f;
    for (int i = tid; i < 2 * D; i += nt) { g_ssum[i] = 0.f; g_smax[i] = 0u; }
}

// ---------------- k_small: hb vectors + ztf ----------------------------------
__global__ void k_small(const float* __restrict__ bq, const float* __restrict__ bk,
                        const float* __restrict__ bv, const float* __restrict__ bo,
                        const float* __restrict__ tb) {
    int w = threadIdx.x >> 5, l = threadIdx.x & 31;
    if (w < 5) {
        const float* bp = (w == 0) ? bq : (w == 1) ? bk : (w == 2) ? bv : (w == 3) ? bo : tb;
        float v[4]; float ss = 0.f;
#pragma unroll
        for (int m = 0; m < 4; ++m) {
            int o = l + 32 * m;
            float x = (o < DOUT) ? bp[o] : 0.f;
            if (w == 4) x = cosf(x);
            v[m] = (o < DOUT) ? x : 0.f;
            ss += v[m] * v[m];
        }
        ss = wsum32(ss);
        float s, en; enc_scale(ss, s, en);
#pragma unroll
        for (int m = 0; m < 4; ++m) {
            int o = l + 32 * m;
            if (o < DOUT) { if (w < 4) g_hb[w * DOUT + o] = v[m] * s; else g_ztf[o] = v[m] * s; }
        }
        if (l == 0) { if (w < 4) g_hb2[w] = en * en; else g_ztf_e2 = en * en; }
    }
}

// ---------------- k1: per-dst encode + Q projection --------------------------
__global__ void __launch_bounds__(256) k1_dst(const float* __restrict__ dst_h,
                                              const float* __restrict__ Wq, int D) {
    extern __shared__ float sm[];
    float* Ws = sm;               // [200][133] -> reused as M [32][104]
    float* Xs = sm + 200 * 133;   // [32][200]
    __shared__ float s_xn[32];
    int t = threadIdx.x, w = t >> 5, l = t & 31;
    int rbase = blockIdx.x * 32;
    float ztf_e2 = g_ztf_e2;
    for (int i = 0; i < 4; ++i) {
        int r = w * 4 + i, gr = rbase + r;
        float* xr = Xs + r * 200;
        if (gr < D) {
            const float* dr = dst_h + (size_t)gr * D_NODE;
            float v[4]; float ss = 0.f;
#pragma unroll
            for (int m = 0; m < 4; ++m) { int o = l + 32 * m; v[m] = (o < 100) ? dr[o] : 0.f; ss += v[m] * v[m]; }
            ss = wsum32(ss);
            float s, en; enc_scale(ss, s, en);
#pragma unroll
            for (int m = 0; m < 4; ++m) {
                int o = l + 32 * m;
                if (o < 100) {
                    float h = v[m] * s;
                    xr[o] = h; xr[100 + o] = g_ztf[o];
                    g_dsthyp[(size_t)gr * 100 + o] = h;
                }
            }
            if (l == 0) s_xn[r] = fmaxf(sqrtf(en * en + ztf_e2), MINN);
        } else {
            for (int o = l; o < 200; o += 32) xr[o] = 0.f;
            if (l == 0) s_xn[r] = MINN;
        }
    }
    for (int i = t; i < 28 * 200; i += 256) { int o = 100 + i / 200, k = i % 200; Ws[k * 133 + o] = 0.f; }
    for (int i = t; i < 100 * 200; i += 256) { int o = i / 200, k = i % 200; Ws[k * 133 + o] = Wq[i]; }
    __syncthreads();
    int oc = t & 127, g = t >> 7;
    float acc[16];
#pragma unroll
    for (int rr = 0; rr < 16; ++rr) acc[rr] = 0.f;
    for (int k = 0; k < 200; ++k) {
        float wv = Ws[k * 133 + oc];
#pragma unroll
        for (int rr = 0; rr < 16; ++rr) acc[rr] = fmaf(Xs[(g * 16 + rr) * 200 + k], wv, acc[rr]);
    }
    __syncthreads();
    float* Ms = Ws;
    if (oc < 100) {
#pragma unroll
        for (int rr = 0; rr < 16; ++rr) Ms[(g * 16 + rr) * 104 + oc] = acc[rr];
    }
    __syncthreads();
    float hb2 = g_hb2[0];
    for (int i = 0; i < 4; ++i) {
        int r = w * 4 + i, gr = rbase + r;
        if (gr >= D) continue;
        float mv[4], hv[4]; float pn = 0.f, pd = 0.f;
#pragma unroll
        for (int m = 0; m < 4; ++m) {
            int o = l + 32 * m;
            float a = (o < 100) ? Ms[r * 104 + o] : 0.f;
            float h = (o < 100) ? g_hb[o] : 0.f;
            mv[m] = a; hv[m] = h; pn += a * a; pd += a * h;
        }
        pn = wsum32(pn); pd = wsum32(pd);
        float alpha, beta, np;
        hyp_ab(pn, s_xn[r], pd, hb2, alpha, beta, np);
#pragma unroll
        for (int m = 0; m < 4; ++m) {
            int o = l + 32 * m;
            if (o < 100) g_Qd[(size_t)gr * 100 + o] = alpha * mv[m] + beta * hv[m];
        }
    }
}

// ---------------- k2: fused edge encode + joint K/V GEMM + scores ------------
// 512 thr: warp = 4 edges (Xs broadcast), thread = 4 cols of K and V.
#define TE    64
#define KC    124
#define WP    132
#define XPAD  380
__global__ void __launch_bounds__(512) k2_edge(
    const float* __restrict__ neigh, const float* __restrict__ edgef,
    const float* __restrict__ dtp, const int* __restrict__ edst,
    const float* __restrict__ Wk, const float* __restrict__ Wv,
    const float* __restrict__ tw, const float* __restrict__ tb, int E) {
    extern __shared__ float sm[];
    float* Xs  = sm;                       // [64][380]
    float* Wks = sm + TE * XPAD;           // [124][132] -> reused as Kt [64][104]
    float* Wvs = Wks + KC * WP;            // [124][132]
    __shared__ float s_xn[TE];
    __shared__ int   s_dst[TE];
    __shared__ float s_hbk[DOUT], s_hbv[DOUT];
    __shared__ float s_hb2k, s_hb2v;
    int t = threadIdx.x, w = t >> 5, l = t & 31;
    int base = blockIdx.x * TE;

    // Phase A: build encoded X rows (16 warps x 4 edges)
    for (int i = 0; i < 4; ++i) {
        int e = w * 4 + i, ge = base + e;
        float* xr = Xs + e * XPAD;
        if (ge < E) {
            float ss, s, e1, e2, e3;
            const float* nr = neigh + (size_t)ge * D_NODE;
            float v[4]; ss = 0.f;
#pragma unroll
            for (int m = 0; m < 4; ++m) { int o = l + 32 * m; v[m] = (o < 100) ? nr[o] : 0.f; ss += v[m] * v[m]; }
            ss = wsum32(ss); enc_scale(ss, s, e1);
#pragma unroll
            for (int m = 0; m < 4; ++m) { int o = l + 32 * m; if (o < 100) xr[o] = v[m] * s; }
            const float* er2 = edgef + (size_t)ge * D_EDGE;
            float u[6]; ss = 0.f;
#pragma unroll
            for (int m = 0; m < 6; ++m) { int o = l + 32 * m; u[m] = (o < 172) ? er2[o] : 0.f; ss += u[m] * u[m]; }
            ss = wsum32(ss); enc_scale(ss, s, e2);
#pragma unroll
            for (int m = 0; m < 6; ++m) { int o = l + 32 * m; if (o < 172) xr[100 + o] = u[m] * s; }
            float dtv = dtp[ge];
            float cc[4]; ss = 0.f;
#pragma unroll
            for (int m = 0; m < 4; ++m) {
                int o = l + 32 * m;
                float c = (o < 100) ? __cosf(fmaf(dtv, tw[o], tb[o])) : 0.f;
                cc[m] = c; ss += c * c;
            }
            ss = wsum32(ss); enc_scale(ss, s, e3);
#pragma unroll
            for (int m = 0; m < 4; ++m) { int o = l + 32 * m; if (o < 100) xr[272 + o] = cc[m] * s; }
            if (l == 0) { s_xn[e] = fmaxf(sqrtf(e1 * e1 + e2 * e2 + e3 * e3), MINN); s_dst[e] = edst[ge]; }
        } else {
            for (int o = l; o < NKV; o += 32) xr[o] = 0.f;
            if (l == 0) { s_xn[e] = MINN; s_dst[e] = 0; }
        }
    }
    for (int o = t; o < DOUT; o += 512) { s_hbk[o] = g_hb[1 * DOUT + o]; s_hbv[o] = g_hb[2 * DOUT + o]; }
    if (t == 0) { s_hb2k = g_hb2[1]; s_hb2v = g_hb2[2]; }
    for (int i = t; i < KC * 28; i += 512) {
        int kk = i / 28, o = 100 + i % 28;
        Wks[kk * WP + o] = 0.f; Wvs[kk * WP + o] = 0.f;
    }

    int oc = (t & 31) * 4;     // 0..124 (pad cols >=100 are zero)
    int er = (t >> 5) * 4;     // warp-uniform edge base
    const float* xrow0 = Xs + er * XPAD;
    float aK[4][4], aV[4][4];
#pragma unroll
    for (int i2 = 0; i2 < 4; ++i2)
#pragma unroll
        for (int j = 0; j < 4; ++j) { aK[i2][j] = 0.f; aV[i2][j] = 0.f; }

    for (int kc = 0; kc < NKV; kc += KC) {
        __syncthreads();
        for (int i = t; i < 100 * KC; i += 512) {
            int o = i / KC, kk = i % KC;
            Wks[kk * WP + o] = Wk[o * NKV + kc + kk];
            Wvs[kk * WP + o] = Wv[o * NKV + kc + kk];
        }
        __syncthreads();
#pragma unroll 2
        for (int kk = 0; kk < KC; ++kk) {
            float4 kw = *(const float4*)(Wks + kk * WP + oc);
            float4 vw = *(const float4*)(Wvs + kk * WP + oc);
            float x0 = xrow0[kc + kk];
            float x1 = xrow0[XPAD + kc + kk];
            float x2 = xrow0[2 * XPAD + kc + kk];
            float x3 = xrow0[3 * XPAD + kc + kk];
            const float* kp = (const float*)&kw;
            const float* vp = (const float*)&vw;
#pragma unroll
            for (int j = 0; j < 4; ++j) {
                aK[0][j] = fmaf(x0, kp[j], aK[0][j]);
                aK[1][j] = fmaf(x1, kp[j], aK[1][j]);
                aK[2][j] = fmaf(x2, kp[j], aK[2][j]);
                aK[3][j] = fmaf(x3, kp[j], aK[3][j]);
                aV[0][j] = fmaf(x0, vp[j], aV[0][j]);
                aV[1][j] = fmaf(x1, vp[j], aV[1][j]);
                aV[2][j] = fmaf(x2, vp[j], aV[2][j]);
                aV[3][j] = fmaf(x3, vp[j], aV[3][j]);
            }
        }
    }

    // epilogue scalars (reduce across warp = full 128-col row per edge)
    float alK[4], beK[4], alV[4], beV[4];
#pragma unroll
    for (int i2 = 0; i2 < 4; ++i2) {
        float pnk = 0.f, pdk = 0.f, pnv = 0.f, pdv = 0.f;
#pragma unroll
        for (int j = 0; j < 4; ++j) {
            int o = oc + j;
            float hk = (o < DOUT) ? s_hbk[o] : 0.f;
            float hv = (o < DOUT) ? s_hbv[o] : 0.f;
            pnk += aK[i2][j] * aK[i2][j]; pdk += aK[i2][j] * hk;
            pnv += aV[i2][j] * aV[i2][j]; pdv += aV[i2][j] * hv;
        }
        pnk = wsum32(pnk); pdk = wsum32(pdk);
        pnv = wsum32(pnv); pdv = wsum32(pdv);
        float np;
        hyp_ab(pnk, s_xn[er + i2], pdk, s_hb2k, alK[i2], beK[i2], np);
        hyp_ab(pnv, s_xn[er + i2], pdv, s_hb2v, alV[i2], beV[i2], np);
    }

    // K tile to smem (reuse Wks), then scores
    __syncthreads();
    float* Kt = Wks;
#pragma unroll
    for (int i2 = 0; i2 < 4; ++i2)
#pragma unroll
        for (int j = 0; j < 4; ++j) {
            int o = oc + j;
            if (o < DOUT) Kt[(er + i2) * 104 + o] = alK[i2] * aK[i2][j] + beK[i2] * s_hbk[o];
        }
    __syncthreads();
    for (int i = 0; i < 4; ++i) {
        int e = w * 4 + i, ge = base + e;
        if (ge >= E) continue;
        int dv = s_dst[e];
        const float* q = g_Qd + (size_t)dv * DOUT;
        float s0 = 0.f, s1v = 0.f;
        for (int o = l; o < DOUT; o += 32) {
            float p = q[o] * Kt[e * 104 + o];
            if (o < 50) s0 += p; else s1v += p;
        }
        s0 = wsum32(s0); s1v = wsum32(s1v);
        if (l == 0) {
            float r0 = lrelu(s0), r1 = lrelu(s1v);
            g_scores[2 * ge] = r0; g_scores[2 * ge + 1] = r1;
            atomicMax(&g_smax[2 * dv], fenc(r0));
            atomicMax(&g_smax[2 * dv + 1], fenc(r1));
        }
    }
    // V to global (one float4 per edge per thread)
#pragma unroll
    for (int i2 = 0; i2 < 4; ++i2) {
        int ge = base + er + i2;
        if (ge >= E || oc >= DOUT) continue;
        float4 r;
        r.x = alV[i2] * aV[i2][0] + beV[i2] * s_hbv[oc + 0];
        r.y = alV[i2] * aV[i2][1] + beV[i2] * s_hbv[oc + 1];
        r.z = alV[i2] * aV[i2][2] + beV[i2] * s_hbv[oc + 2];
        r.w = alV[i2] * aV[i2][3] + beV[i2] * s_hbv[oc + 3];
        *(float4*)(g_V + (size_t)ge * DOUT + oc) = r;
    }
}

// ---------------- k3: exp + segment sum --------------------------------------
__global__ void k3_exp(const int* __restrict__ edst, int E) {
    int e = blockIdx.x * blockDim.x + threadIdx.x;
    if (e >= E) return;
    int d = edst[e];
    float z0 = __expf(g_scores[2 * e] - fdec(g_smax[2 * d]));
    float z1 = __expf(g_scores[2 * e + 1] - fdec(g_smax[2 * d + 1]));
    g_ez[2 * e] = z0; g_ez[2 * e + 1] = z1;
    atomicAdd(&g_ssum[2 * d], z0);
    atomicAdd(&g_ssum[2 * d + 1], z1);
}

// ---------------- k4: weighted scatter aggregate (vector red) ----------------
__global__ void k4_agg(const int* __restrict__ edst, int E) {
    int gw = (blockIdx.x * blockDim.x + threadIdx.x) >> 5;
    int l = threadIdx.x & 31;
    if (gw >= E) return;
    int d = edst[gw];
    float a0 = g_ez[2 * gw] / fmaxf(g_ssum[2 * d], MINN);
    float a1 = g_ez[2 * gw + 1] / fmaxf(g_ssum[2 * d + 1], MINN);
    if (l < 25) {
        const float4* vr = (const float4*)(g_V + (size_t)gw * DOUT);
        float4 v = vr[l];
        int c0 = 4 * l;
        float4 r;
        r.x = v.x * (c0 + 0 < 50 ? a0 : a1);
        r.y = v.y * (c0 + 1 < 50 ? a0 : a1);
        r.z = v.z * (c0 + 2 < 50 ? a0 : a1);
        r.w = v.w * (c0 + 3 < 50 ? a0 : a1);
        float* hp = g_hagg + (size_t)d * DOUT + c0;
        asm volatile("red.global.add.v4.f32 [%0], {%1, %2, %3, %4};"
                     :: "l"(hp), "f"(r.x), "f"(r.y), "f"(r.z), "f"(r.w) : "memory");
    }
}

// ---------------- k5: O projection + HypAct + logmap0 + LayerNorm ------------
__global__ void __launch_bounds__(256) k5_final(const float* __restrict__ Wo,
                                                const float* __restrict__ lng,
                                                const float* __restrict__ lnb,
                                                float* __restrict__ out, int D) {
    extern __shared__ float sm[];
    float* Ws = sm;
    float* Xs = sm + 200 * 133;
    __shared__ float s_xn[32];
    int t = threadIdx.x, w = t >> 5, l = t & 31;
    int rbase = blockIdx.x * 32;
    for (int i = 0; i < 4; ++i) {
        int r = w * 4 + i, gr = rbase + r;
        float* xr = Xs + r * 200;
        if (gr < D) {
            const float* ha = g_hagg + (size_t)gr * DOUT;
            const float* dh = g_dsthyp + (size_t)gr * D_NODE;
            float ss = 0.f;
#pragma unroll
            for (int m = 0; m < 4; ++m) {
                int o = l + 32 * m;
                float a = (o < 100) ? ha[o] : 0.f;
                float b = (o < 100) ? dh[o] : 0.f;
                if (o < 100) { xr[o] = a; xr[100 + o] = b; }
                ss += a * a + b * b;
            }
            ss = wsum32(ss);
            if (l == 0) s_xn[r] = fmaxf(sqrtf(ss), MINN);
        } else {
            for (int o = l; o < 200; o += 32) xr[o] = 0.f;
            if (l == 0) s_xn[r] = MINN;
        }
    }
    for (int i = t; i < 28 * 200; i += 256) { int o = 100 + i / 200, k = i % 200; Ws[k * 133 + o] = 0.f; }
    for (int i = t; i < 100 * 200; i += 256) { int o = i / 200, k = i % 200; Ws[k * 133 + o] = Wo[i]; }
    __syncthreads();
    int oc = t & 127, g = t >> 7;
    float acc[16];
#pragma unroll
    for (int rr = 0; rr < 16; ++rr) acc[rr] = 0.f;
    for (int k = 0; k < 200; ++k) {
        float wv = Ws[k * 133 + oc];
#pragma unroll
        for (int rr = 0; rr < 16; ++rr) acc[rr] = fmaf(Xs[(g * 16 + rr) * 200 + k], wv, acc[rr]);
    }
    __syncthreads();
    float* Ms = Ws;
    if (oc < 100) {
#pragma unroll
        for (int rr = 0; rr < 16; ++rr) Ms[(g * 16 + rr) * 104 + oc] = acc[rr];
    }
    __syncthreads();
    float hb2 = g_hb2[3];
    for (int i = 0; i < 4; ++i) {
        int r = w * 4 + i, gr = rbase + r;
        if (gr >= D) continue;
        float mv[4], hv[4]; float pn = 0.f, pd = 0.f;
#pragma unroll
        for (int m = 0; m < 4; ++m) {
            int o = l + 32 * m;
            float a = (o < 100) ? Ms[r * 104 + o] : 0.f;
            float h = (o < 100) ? g_hb[3 * DOUT + o] : 0.f;
            mv[m] = a; hv[m] = h; pn += a * a; pd += a * h;
        }
        pn = wsum32(pn); pd = wsum32(pd);
        float alpha, beta, nprev;
        hyp_ab(pn, s_xn[r], pd, hb2, alpha, beta, nprev);
        float lc = artanh_f(nprev) / fmaxf(nprev, MINN);
        float u2v[4]; float uss = 0.f;
#pragma unroll
        for (int m = 0; m < 4; ++m) {
            float u2 = lrelu(lc * (alpha * mv[m] + beta * hv[m]));
            u2v[m] = u2; uss += u2 * u2;
        }
        uss = wsum32(uss);
        float s2, en3; enc_scale(uss, s2, en3);
        float hsc = artanh_f(en3) / fmaxf(en3, MINN) * s2;
        float hvv[4]; float hs = 0.f, hs2 = 0.f;
#pragma unroll
        for (int m = 0; m < 4; ++m) {
            int o = l + 32 * m;
            float h = hsc * u2v[m];
            hvv[m] = h;
            if (o < 100) { hs += h; hs2 += h * h; }
        }
        hs = wsum32(hs); hs2 = wsum32(hs2);
        float mu = hs * 0.01f;
        float var = hs2 * 0.01f - mu * mu;
        float inv = rsqrtf(var + 1e-5f);
#pragma unroll
        for (int m = 0; m < 4; ++m) {
            int o = l + 32 * m;
            if (o < 100) out[(size_t)gr * 100 + o] = (hvv[m] - mu) * inv * lng[o] + lnb[o];
        }
    }
}

extern "C" void kernel_launch(void* const* d_in, const int* in_sizes, int n_in,
                              void* d_out, int out_size) {
    const float* dst_h = (const float*)d_in[0];
    const float* neigh = (const float*)d_in[1];
    const float* edgef = (const float*)d_in[2];
    const float* dtp   = (const float*)d_in[3];
    const int*   edst  = (const int*)d_in[4];
    const float* Wq = (const float*)d_in[5];
    const float* bq = (const float*)d_in[6];
    const float* Wk = (const float*)d_in[7];
    const float* bk = (const float*)d_in[8];
    const float* Wv = (const float*)d_in[9];
    const float* bv = (const float*)d_in[10];
    const float* Wo = (const float*)d_in[11];
    const float* bo = (const float*)d_in[12];
    const float* tw = (const float*)d_in[13];
    const float* tb = (const float*)d_in[14];
    const float* lng = (const float*)d_in[15];
    const float* lnb = (const float*)d_in[16];
    float* out = (float*)d_out;
    int D = in_sizes[0] / D_NODE;
    int E = in_sizes[3];

    size_t smem1 = (200 * 133 + 32 * 200) * sizeof(float);          // 132000
    size_t smem2 = (TE * XPAD + 2 * KC * WP) * sizeof(float);       // 228224
    cudaFuncSetAttribute(k1_dst,   cudaFuncAttributeMaxDynamicSharedMemorySize, (int)smem1);
    cudaFuncSetAttribute(k5_final, cudaFuncAttributeMaxDynamicSharedMemorySize, (int)smem1);
    cudaFuncSetAttribute(k2_edge,  cudaFuncAttributeMaxDynamicSharedMemorySize, (int)smem2);

    k_zero<<<2048, 256>>>(D);
    k_small<<<1, 160>>>(bq, bk, bv, bo, tb);
    k1_dst<<<(D + 31) / 32, 256, smem1>>>(dst_h, Wq, D);
    k2_edge<<<(E + TE - 1) / TE, 512, smem2>>>(neigh, edgef, dtp, edst, Wk, Wv, tw, tb, E);
    k3_exp<<<(E + 255) / 256, 256>>>(edst, E);
    k4_agg<<<(E + 7) / 8, 256>>>(edst, E);
    k5_final<<<(D + 31) / 32, 256, smem1>>>(Wo, lng, lnb, out, D);
}

// round 9
// speedup vs baseline: 3.6141x; 1.4412x over previous
#include <cuda_runtime.h>
#include <math.h>
#include <stdint.h>

#define D_NODE 100
#define D_EDGE 172
#define D_TIME 100
#define NKV    372
#define DOUT   100
#define EMAX   320000
#define DMAX   20000
#define MINN   1e-15f
#define MAXN   0.996f
#define SLOPE  0.2f

__device__ float    g_Qd[DMAX * DOUT];
__device__ float    g_dsthyp[DMAX * D_NODE];
__device__ float    g_V[(size_t)EMAX * DOUT];
__device__ float    g_scores[EMAX * 2];
__device__ float    g_ez[EMAX * 2];
__device__ unsigned g_smax[DMAX * 2];
__device__ float    g_ssum[DMAX * 2];
__device__ float    g_hagg[DMAX * DOUT];
__device__ float    g_hb[4 * DOUT];
__device__ float    g_hb2[4];
__device__ float    g_ztf[D_TIME];
__device__ float    g_ztf_e2;

__device__ __forceinline__ float wsum32(float v) {
#pragma unroll
    for (int m = 16; m; m >>= 1) v += __shfl_xor_sync(0xffffffffu, v, m);
    return v;
}
__device__ __forceinline__ float artanh_f(float x) {
    x = fminf(fmaxf(x, -1.0f + 1e-7f), 1.0f - 1e-7f);
    return 0.5f * (log1pf(x) - log1pf(-x));
}
__device__ __forceinline__ void enc_scale(float ss, float& s, float& en) {
    float n = sqrtf(ss), nn = fmaxf(n, MINN);
    float t = tanhf(nn);
    en = fminf(t, MAXN);
    s = en / nn;
}
__device__ __forceinline__ void hyp_ab(float mxn2, float xn, float dot_mh, float hb2,
                                       float& alpha, float& beta, float& nprev) {
    float mxn = fmaxf(sqrtf(mxn2), MINN);
    float t = tanhf(mxn / xn * artanh_f(xn));
    float nres = fminf(t, MAXN);
    float s1 = nres / mxn;
    float x2 = nres * nres;
    float xy = s1 * dot_mh;
    float a = 1.f + 2.f * xy + hb2;
    float bb = 1.f - x2;
    float den = fmaxf(1.f + 2.f * xy + x2 * hb2, MINN);
    float n2 = fmaxf(a * a * x2 + 2.f * a * bb * xy + bb * bb * hb2, 0.f);
    float nout = sqrtf(n2) / den;
    float ps = nout > MAXN ? MAXN / nout : 1.f;
    alpha = ps * a * s1 / den;
    beta = ps * bb / den;
    nprev = fminf(nout, MAXN);
}
__device__ __forceinline__ unsigned fenc(float f) {
    unsigned b = __float_as_uint(f);
    return (b & 0x80000000u) ? ~b : (b | 0x80000000u);
}
__device__ __forceinline__ float fdec(unsigned u) {
    return __uint_as_float((u & 0x80000000u) ? (u & 0x7fffffffu) : ~u);
}
__device__ __forceinline__ float lrelu(float x) { return x > 0.f ? x : SLOPE * x; }
__device__ __forceinline__ float tf32r(float x) {
    uint32_t u;
    asm("cvt.rna.tf32.f32 %0, %1;" : "=r"(u) : "f"(x));
    return __uint_as_float(u);
}
__device__ __forceinline__ void mma_tf32(float* d, const uint32_t* a, const uint32_t* b) {
    asm volatile(
        "mma.sync.aligned.m16n8k8.row.col.f32.tf32.tf32.f32 "
        "{%0,%1,%2,%3}, {%4,%5,%6,%7}, {%8,%9}, {%0,%1,%2,%3};"
        : "+f"(d[0]), "+f"(d[1]), "+f"(d[2]), "+f"(d[3])
        : "r"(a[0]), "r"(a[1]), "r"(a[2]), "r"(a[3]), "r"(b[0]), "r"(b[1]));
}

// ---------------- k0 / k_small ----------------------------------------------
__global__ void k_zero(int D) {
    int tid = blockIdx.x * blockDim.x + threadIdx.x;
    int nt = gridDim.x * blockDim.x;
    for (int i = tid; i < D * DOUT; i += nt) g_hagg[i] = 0.f;
    for (int i = tid; i < 2 * D; i += nt) { g_ssum[i] = 0.f; g_smax[i] = 0u; }
}
__global__ void k_small(const float* __restrict__ bq, const float* __restrict__ bk,
                        const float* __restrict__ bv, const float* __restrict__ bo,
                        const float* __restrict__ tb) {
    int w = threadIdx.x >> 5, l = threadIdx.x & 31;
    if (w < 5) {
        const float* bp = (w == 0) ? bq : (w == 1) ? bk : (w == 2) ? bv : (w == 3) ? bo : tb;
        float v[4]; float ss = 0.f;
#pragma unroll
        for (int m = 0; m < 4; ++m) {
            int o = l + 32 * m;
            float x = (o < DOUT) ? bp[o] : 0.f;
            if (w == 4) x = cosf(x);
            v[m] = (o < DOUT) ? x : 0.f;
            ss += v[m] * v[m];
        }
        ss = wsum32(ss);
        float s, en; enc_scale(ss, s, en);
#pragma unroll
        for (int m = 0; m < 4; ++m) {
            int o = l + 32 * m;
            if (o < DOUT) { if (w < 4) g_hb[w * DOUT + o] = v[m] * s; else g_ztf[o] = v[m] * s; }
        }
        if (l == 0) { if (w < 4) g_hb2[w] = en * en; else g_ztf_e2 = en * en; }
    }
}

// ---------------- k1: per-dst encode + Q projection --------------------------
__global__ void __launch_bounds__(256) k1_dst(const float* __restrict__ dst_h,
                                              const float* __restrict__ Wq, int D) {
    extern __shared__ float sm[];
    float* Ws = sm;
    float* Xs = sm + 200 * 133;
    __shared__ float s_xn[32];
    int t = threadIdx.x, w = t >> 5, l = t & 31;
    int rbase = blockIdx.x * 32;
    float ztf_e2 = g_ztf_e2;
    for (int i = 0; i < 4; ++i) {
        int r = w * 4 + i, gr = rbase + r;
        float* xr = Xs + r * 200;
        if (gr < D) {
            const float* dr = dst_h + (size_t)gr * D_NODE;
            float v[4]; float ss = 0.f;
#pragma unroll
            for (int m = 0; m < 4; ++m) { int o = l + 32 * m; v[m] = (o < 100) ? dr[o] : 0.f; ss += v[m] * v[m]; }
            ss = wsum32(ss);
            float s, en; enc_scale(ss, s, en);
#pragma unroll
            for (int m = 0; m < 4; ++m) {
                int o = l + 32 * m;
                if (o < 100) {
                    float h = v[m] * s;
                    xr[o] = h; xr[100 + o] = g_ztf[o];
                    g_dsthyp[(size_t)gr * 100 + o] = h;
                }
            }
            if (l == 0) s_xn[r] = fmaxf(sqrtf(en * en + ztf_e2), MINN);
        } else {
            for (int o = l; o < 200; o += 32) xr[o] = 0.f;
            if (l == 0) s_xn[r] = MINN;
        }
    }
    for (int i = t; i < 28 * 200; i += 256) { int o = 100 + i / 200, k = i % 200; Ws[k * 133 + o] = 0.f; }
    for (int i = t; i < 100 * 200; i += 256) { int o = i / 200, k = i % 200; Ws[k * 133 + o] = Wq[i]; }
    __syncthreads();
    int oc = t & 127, g = t >> 7;
    float acc[16];
#pragma unroll
    for (int rr = 0; rr < 16; ++rr) acc[rr] = 0.f;
    for (int k = 0; k < 200; ++k) {
        float wv = Ws[k * 133 + oc];
#pragma unroll
        for (int rr = 0; rr < 16; ++rr) acc[rr] = fmaf(Xs[(g * 16 + rr) * 200 + k], wv, acc[rr]);
    }
    __syncthreads();
    float* Ms = Ws;
    if (oc < 100) {
#pragma unroll
        for (int rr = 0; rr < 16; ++rr) Ms[(g * 16 + rr) * 104 + oc] = acc[rr];
    }
    __syncthreads();
    float hb2 = g_hb2[0];
    for (int i = 0; i < 4; ++i) {
        int r = w * 4 + i, gr = rbase + r;
        if (gr >= D) continue;
        float mv[4], hv[4]; float pn = 0.f, pd = 0.f;
#pragma unroll
        for (int m = 0; m < 4; ++m) {
            int o = l + 32 * m;
            float a = (o < 100) ? Ms[r * 104 + o] : 0.f;
            float h = (o < 100) ? g_hb[o] : 0.f;
            mv[m] = a; hv[m] = h; pn += a * a; pd += a * h;
        }
        pn = wsum32(pn); pd = wsum32(pd);
        float alpha, beta, np;
        hyp_ab(pn, s_xn[r], pd, hb2, alpha, beta, np);
#pragma unroll
        for (int m = 0; m < 4; ++m) {
            int o = l + 32 * m;
            if (o < 100) g_Qd[(size_t)gr * 100 + o] = alpha * mv[m] + beta * hv[m];
        }
    }
}

// ---------------- k2: mma.sync tf32 edge kernel ------------------------------
// 64 edges/CTA, 512 thr. Xs = A fragments [4 mt][48 ks][32 lane][4].
// Bs = B fragments per 12-kstep chunk [2 mat][16 nt][12 ksl][32 lane][2].
#define TE 64
__device__ __forceinline__ void xs_store(float* Xs, int e, int f, float v) {
    int mt = e >> 4, r = e & 15, ks = f >> 3, c = f & 7;
    int lane_t = ((r & 7) << 2) | (c & 3);
    int ii = ((c >> 2) << 1) | (r >> 3);
    Xs[(((mt * 48 + ks) << 5) + lane_t) * 4 + ii] = tf32r(v);
}
__global__ void __launch_bounds__(512) k2_edge(
    const float* __restrict__ neigh, const float* __restrict__ edgef,
    const float* __restrict__ dtp, const int* __restrict__ edst,
    const float* __restrict__ Wk, const float* __restrict__ Wv,
    const float* __restrict__ tw, const float* __restrict__ tb, int E) {
    extern __shared__ float sm[];
    float* Xs = sm;            // 24576 floats
    float* Bs = sm + 24576;    // 24576 floats
    __shared__ float s_xn[TE];
    __shared__ int   s_dst[TE];
    __shared__ float s_hbk[DOUT], s_hbv[DOUT];
    __shared__ float s_hb2k, s_hb2v;
    int t = threadIdx.x, w = t >> 5, l = t & 31;
    int base = blockIdx.x * TE;

    // Phase A: encode 4 edges per warp into A-fragment layout
    for (int i = 0; i < 4; ++i) {
        int e = w * 4 + i, ge = base + e;
        if (ge < E) {
            float ss, s, e1, e2, e3;
            const float* nr = neigh + (size_t)ge * D_NODE;
            float v[4]; ss = 0.f;
#pragma unroll
            for (int m = 0; m < 4; ++m) { int o = l + 32 * m; v[m] = (o < 100) ? nr[o] : 0.f; ss += v[m] * v[m]; }
            ss = wsum32(ss); enc_scale(ss, s, e1);
#pragma unroll
            for (int m = 0; m < 4; ++m) { int o = l + 32 * m; if (o < 100) xs_store(Xs, e, o, v[m] * s); }
            const float* er2 = edgef + (size_t)ge * D_EDGE;
            float u[6]; ss = 0.f;
#pragma unroll
            for (int m = 0; m < 6; ++m) { int o = l + 32 * m; u[m] = (o < 172) ? er2[o] : 0.f; ss += u[m] * u[m]; }
            ss = wsum32(ss); enc_scale(ss, s, e2);
#pragma unroll
            for (int m = 0; m < 6; ++m) { int o = l + 32 * m; if (o < 172) xs_store(Xs, e, 100 + o, u[m] * s); }
            float dtv = dtp[ge];
            float cc[4]; ss = 0.f;
#pragma unroll
            for (int m = 0; m < 4; ++m) {
                int o = l + 32 * m;
                float c = (o < 100) ? __cosf(fmaf(dtv, tw[o], tb[o])) : 0.f;
                cc[m] = c; ss += c * c;
            }
            ss = wsum32(ss); enc_scale(ss, s, e3);
#pragma unroll
            for (int m = 0; m < 4; ++m) { int o = l + 32 * m; if (o < 100) xs_store(Xs, e, 272 + o, cc[m] * s); }
            if (l < 12) xs_store(Xs, e, 372 + l, 0.f);
            if (l == 0) { s_xn[e] = fmaxf(sqrtf(e1 * e1 + e2 * e2 + e3 * e3), MINN); s_dst[e] = edst[ge]; }
        } else {
            for (int o = l; o < 384; o += 32) xs_store(Xs, e, o, 0.f);
            if (l == 0) { s_xn[e] = MINN; s_dst[e] = 0; }
        }
    }
    for (int o = t; o < DOUT; o += 512) { s_hbk[o] = g_hb[1 * DOUT + o]; s_hbv[o] = g_hb[2 * DOUT + o]; }
    if (t == 0) { s_hb2k = g_hb2[1]; s_hb2v = g_hb2[2]; }

    // GEMM: warp = (mat, mgroup of 2 mtiles, ngroup of 4 ntiles)
    int mat = w >> 3, mg = (w >> 2) & 1, ng = w & 3;
    float acc[2][4][4];
#pragma unroll
    for (int a = 0; a < 2; ++a)
#pragma unroll
        for (int b = 0; b < 4; ++b)
#pragma unroll
            for (int cxx = 0; cxx < 4; ++cxx) acc[a][b][cxx] = 0.f;

    for (int c = 0; c < 4; ++c) {
        __syncthreads();   // prior compute done (or encode for c=0) before Bs overwrite
        for (int i = t; i < 24576; i += 512) {
            int nm = i / 96, kfl = i % 96;
            int mm = nm >> 7, n = nm & 127;
            int kf = c * 96 + kfl;
            float v = 0.f;
            if (n < 100 && kf < NKV) v = (mm ? Wv : Wk)[n * NKV + kf];
            int ksl = kfl >> 3, kc8 = kfl & 7;
            int lane_t = ((n & 7) << 2) | (kc8 & 3);
            int ii = kc8 >> 2;
            Bs[((((mm << 4) | (n >> 3)) * 12 + ksl) * 32 + lane_t) * 2 + ii] = tf32r(v);
        }
        __syncthreads();
#pragma unroll
        for (int ksl = 0; ksl < 12; ++ksl) {
            int ks = c * 12 + ksl;
            uint32_t a0[4], a1[4];
            *(float4*)a0 = *(const float4*)(Xs + (((2 * mg) * 48 + ks) * 32 + l) * 4);
            *(float4*)a1 = *(const float4*)(Xs + (((2 * mg + 1) * 48 + ks) * 32 + l) * 4);
#pragma unroll
            for (int nt4 = 0; nt4 < 4; ++nt4) {
                int nt = ng * 4 + nt4;
                uint32_t b[2];
                *(float2*)b = *(const float2*)(Bs + (((mat * 16 + nt) * 12 + ksl) * 32 + l) * 2);
                mma_tf32(acc[0][nt4], a0, b);
                mma_tf32(acc[1][nt4], a1, b);
            }
        }
    }
    __syncthreads();   // all done reading Xs; reuse it for K/V tiles
    float* Kt = Xs;               // [64][104]
    float* Vt = Xs + TE * 104;    // [64][104]
#pragma unroll
    for (int mi = 0; mi < 2; ++mi) {
        int r0 = (2 * mg + mi) * 16 + (l >> 2);
        float* dst = mat ? Vt : Kt;
#pragma unroll
        for (int nt4 = 0; nt4 < 4; ++nt4) {
            int ncol = ng * 32 + nt4 * 8 + (l & 3) * 2;
            if (ncol < 100) {
                dst[r0 * 104 + ncol]           = acc[mi][nt4][0];
                dst[r0 * 104 + ncol + 1]       = acc[mi][nt4][1];
                dst[(r0 + 8) * 104 + ncol]     = acc[mi][nt4][2];
                dst[(r0 + 8) * 104 + ncol + 1] = acc[mi][nt4][3];
            }
        }
    }
    __syncthreads();

    // Epilogue: per-edge hyperbolic rescale of K and V rows (in smem)
    float hb2k = s_hb2k, hb2v = s_hb2v;
    for (int i = 0; i < 4; ++i) {
        int e = w * 4 + i;
        float pnk = 0.f, pdk = 0.f, pnv = 0.f, pdv = 0.f;
        for (int o = l; o < DOUT; o += 32) {
            float kv = Kt[e * 104 + o], vv = Vt[e * 104 + o];
            pnk += kv * kv; pdk += kv * s_hbk[o];
            pnv += vv * vv; pdv += vv * s_hbv[o];
        }
        pnk = wsum32(pnk); pdk = wsum32(pdk);
        pnv = wsum32(pnv); pdv = wsum32(pdv);
        float alK, beK, alV, beV, np;
        hyp_ab(pnk, s_xn[e], pdk, hb2k, alK, beK, np);
        hyp_ab(pnv, s_xn[e], pdv, hb2v, alV, beV, np);
        for (int o = l; o < DOUT; o += 32) {
            Kt[e * 104 + o] = alK * Kt[e * 104 + o] + beK * s_hbk[o];
            Vt[e * 104 + o] = alV * Vt[e * 104 + o] + beV * s_hbv[o];
        }
    }
    __syncthreads();

    // Scores: 16 warps x 4 edges
    for (int i = 0; i < 4; ++i) {
        int e = w * 4 + i, ge = base + e;
        if (ge >= E) continue;
        int dv = s_dst[e];
        const float* q = g_Qd + (size_t)dv * DOUT;
        float s0 = 0.f, s1v = 0.f;
        for (int o = l; o < DOUT; o += 32) {
            float p = q[o] * Kt[e * 104 + o];
            if (o < 50) s0 += p; else s1v += p;
        }
        s0 = wsum32(s0); s1v = wsum32(s1v);
        if (l == 0) {
            float r0 = lrelu(s0), r1 = lrelu(s1v);
            g_scores[2 * ge] = r0; g_scores[2 * ge + 1] = r1;
            atomicMax(&g_smax[2 * dv], fenc(r0));
            atomicMax(&g_smax[2 * dv + 1], fenc(r1));
        }
    }
    // Coalesced V writeout
    for (int i = t; i < TE * 25; i += 512) {
        int e = i / 25, c4 = i % 25;
        int ge = base + e;
        if (ge < E) {
            float4 v = *(const float4*)(Vt + e * 104 + c4 * 4);
            *(float4*)(g_V + (size_t)ge * DOUT + c4 * 4) = v;
        }
    }
}

// ---------------- k3: exp + segment sum --------------------------------------
__global__ void k3_exp(const int* __restrict__ edst, int E) {
    int e = blockIdx.x * blockDim.x + threadIdx.x;
    if (e >= E) return;
    int d = edst[e];
    float z0 = __expf(g_scores[2 * e] - fdec(g_smax[2 * d]));
    float z1 = __expf(g_scores[2 * e + 1] - fdec(g_smax[2 * d + 1]));
    g_ez[2 * e] = z0; g_ez[2 * e + 1] = z1;
    atomicAdd(&g_ssum[2 * d], z0);
    atomicAdd(&g_ssum[2 * d + 1], z1);
}

// ---------------- k4: weighted scatter aggregate -----------------------------
__global__ void k4_agg(const int* __restrict__ edst, int E) {
    int gw = (blockIdx.x * blockDim.x + threadIdx.x) >> 5;
    int l = threadIdx.x & 31;
    if (gw >= E) return;
    int d = edst[gw];
    float a0 = g_ez[2 * gw] / fmaxf(g_ssum[2 * d], MINN);
    float a1 = g_ez[2 * gw + 1] / fmaxf(g_ssum[2 * d + 1], MINN);
    if (l < 25) {
        const float4* vr = (const float4*)(g_V + (size_t)gw * DOUT);
        float4 v = vr[l];
        int c0 = 4 * l;
        float4 r;
        r.x = v.x * (c0 + 0 < 50 ? a0 : a1);
        r.y = v.y * (c0 + 1 < 50 ? a0 : a1);
        r.z = v.z * (c0 + 2 < 50 ? a0 : a1);
        r.w = v.w * (c0 + 3 < 50 ? a0 : a1);
        float* hp = g_hagg + (size_t)d * DOUT + c0;
        asm volatile("red.global.add.v4.f32 [%0], {%1, %2, %3, %4};"
                     :: "l"(hp), "f"(r.x), "f"(r.y), "f"(r.z), "f"(r.w) : "memory");
    }
}

// ---------------- k5: O projection + HypAct + logmap0 + LayerNorm ------------
__global__ void __launch_bounds__(256) k5_final(const float* __restrict__ Wo,
                                                const float* __restrict__ lng,
                                                const float* __restrict__ lnb,
                                                float* __restrict__ out, int D) {
    extern __shared__ float sm[];
    float* Ws = sm;
    float* Xs = sm + 200 * 133;
    __shared__ float s_xn[32];
    int t = threadIdx.x, w = t >> 5, l = t & 31;
    int rbase = blockIdx.x * 32;
    for (int i = 0; i < 4; ++i) {
        int r = w * 4 + i, gr = rbase + r;
        float* xr = Xs + r * 200;
        if (gr < D) {
            const float* ha = g_hagg + (size_t)gr * DOUT;
            const float* dh = g_dsthyp + (size_t)gr * D_NODE;
            float ss = 0.f;
#pragma unroll
            for (int m = 0; m < 4; ++m) {
                int o = l + 32 * m;
                float a = (o < 100) ? ha[o] : 0.f;
                float b = (o < 100) ? dh[o] : 0.f;
                if (o < 100) { xr[o] = a; xr[100 + o] = b; }
                ss += a * a + b * b;
            }
            ss = wsum32(ss);
            if (l == 0) s_xn[r] = fmaxf(sqrtf(ss), MINN);
        } else {
            for (int o = l; o < 200; o += 32) xr[o] = 0.f;
            if (l == 0) s_xn[r] = MINN;
        }
    }
    for (int i = t; i < 28 * 200; i += 256) { int o = 100 + i / 200, k = i % 200; Ws[k * 133 + o] = 0.f; }
    for (int i = t; i < 100 * 200; i += 256) { int o = i / 200, k = i % 200; Ws[k * 133 + o] = Wo[i]; }
    __syncthreads();
    int oc = t & 127, g = t >> 7;
    float acc[16];
#pragma unroll
    for (int rr = 0; rr < 16; ++rr) acc[rr] = 0.f;
    for (int k = 0; k < 200; ++k) {
        float wv = Ws[k * 133 + oc];
#pragma unroll
        for (int rr = 0; rr < 16; ++rr) acc[rr] = fmaf(Xs[(g * 16 + rr) * 200 + k], wv, acc[rr]);
    }
    __syncthreads();
    float* Ms = Ws;
    if (oc < 100) {
#pragma unroll
        for (int rr = 0; rr < 16; ++rr) Ms[(g * 16 + rr) * 104 + oc] = acc[rr];
    }
    __syncthreads();
    float hb2 = g_hb2[3];
    for (int i = 0; i < 4; ++i) {
        int r = w * 4 + i, gr = rbase + r;
        if (gr >= D) continue;
        float mv[4], hv[4]; float pn = 0.f, pd = 0.f;
#pragma unroll
        for (int m = 0; m < 4; ++m) {
            int o = l + 32 * m;
            float a = (o < 100) ? Ms[r * 104 + o] : 0.f;
            float h = (o < 100) ? g_hb[3 * DOUT + o] : 0.f;
            mv[m] = a; hv[m] = h; pn += a * a; pd += a * h;
        }
        pn = wsum32(pn); pd = wsum32(pd);
        float alpha, beta, nprev;
        hyp_ab(pn, s_xn[r], pd, hb2, alpha, beta, nprev);
        float lc = artanh_f(nprev) / fmaxf(nprev, MINN);
        float u2v[4]; float uss = 0.f;
#pragma unroll
        for (int m = 0; m < 4; ++m) {
            float u2 = lrelu(lc * (alpha * mv[m] + beta * hv[m]));
            u2v[m] = u2; uss += u2 * u2;
        }
        uss = wsum32(uss);
        float s2, en3; enc_scale(uss, s2, en3);
        float hsc = artanh_f(en3) / fmaxf(en3, MINN) * s2;
        float hvv[4]; float hs = 0.f, hs2 = 0.f;
#pragma unroll
        for (int m = 0; m < 4; ++m) {
            int o = l + 32 * m;
            float h = hsc * u2v[m];
            hvv[m] = h;
            if (o < 100) { hs += h; hs2 += h * h; }
        }
        hs = wsum32(hs); hs2 = wsum32(hs2);
        float mu = hs * 0.01f;
        float var = hs2 * 0.01f - mu * mu;
        float inv = rsqrtf(var + 1e-5f);
#pragma unroll
        for (int m = 0; m < 4; ++m) {
            int o = l + 32 * m;
            if (o < 100) out[(size_t)gr * 100 + o] = (hvv[m] - mu) * inv * lng[o] + lnb[o];
        }
    }
}

extern "C" void kernel_launch(void* const* d_in, const int* in_sizes, int n_in,
                              void* d_out, int out_size) {
    const float* dst_h = (const float*)d_in[0];
    const float* neigh = (const float*)d_in[1];
    const float* edgef = (const float*)d_in[2];
    const float* dtp   = (const float*)d_in[3];
    const int*   edst  = (const int*)d_in[4];
    const float* Wq = (const float*)d_in[5];
    const float* bq = (const float*)d_in[6];
    const float* Wk = (const float*)d_in[7];
    const float* bk = (const float*)d_in[8];
    const float* Wv = (const float*)d_in[9];
    const float* bv = (const float*)d_in[10];
    const float* Wo = (const float*)d_in[11];
    const float* bo = (const float*)d_in[12];
    const float* tw = (const float*)d_in[13];
    const float* tb = (const float*)d_in[14];
    const float* lng = (const float*)d_in[15];
    const float* lnb = (const float*)d_in[16];
    float* out = (float*)d_out;
    int D = in_sizes[0] / D_NODE;
    int E = in_sizes[3];

    size_t smem1 = (200 * 133 + 32 * 200) * sizeof(float);   // 132000
    size_t smem2 = 2 * 24576 * sizeof(float);                // 196608
    cudaFuncSetAttribute(k1_dst,   cudaFuncAttributeMaxDynamicSharedMemorySize, (int)smem1);
    cudaFuncSetAttribute(k5_final, cudaFuncAttributeMaxDynamicSharedMemorySize, (int)smem1);
    cudaFuncSetAttribute(k2_edge,  cudaFuncAttributeMaxDynamicSharedMemorySize, (int)smem2);

    k_zero<<<2048, 256>>>(D);
    k_small<<<1, 160>>>(bq, bk, bv, bo, tb);
    k1_dst<<<(D + 31) / 32, 256, smem1>>>(dst_h, Wq, D);
    k2_edge<<<(E + TE - 1) / TE, 512, smem2>>>(neigh, edgef, dtp, edst, Wk, Wv, tw, tb, E);
    k3_exp<<<(E + 255) / 256, 256>>>(edst, E);
    k4_agg<<<(E + 7) / 8, 256>>>(edst, E);
    k5_final<<<(D + 31) / 32, 256, smem1>>>(Wo, lng, lnb, out, D);
}